// round 1
// baseline (speedup 1.0000x reference)
#include <cuda_runtime.h>
#include <cuda_bf16.h>

#define B_SZ 4
#define T_SZ 1024
#define C_SZ 512
#define H_SZ 8
#define D_SZ 64

// Scratch (static device globals — no allocation)
__device__ float g_q[B_SZ * H_SZ * T_SZ * D_SZ];
__device__ float g_k[B_SZ * H_SZ * T_SZ * D_SZ];
__device__ float g_v[B_SZ * H_SZ * T_SZ * D_SZ];
__device__ float g_att[B_SZ * T_SZ * C_SZ];

// ---------------------------------------------------------------------------
// GEMM: [4096 x 512] @ [512 x 512] + bias
// mode 0/1/2: write q/k/v in [b][h][t][d] layout; mode 3: A = g_att, write
// row-major to out_ext.
// Tile: BM=128, BN=64, BK=32, 256 threads, 8x4 microtile per thread.
// ---------------------------------------------------------------------------
__global__ __launch_bounds__(256) void gemm512_kernel(
    const float* __restrict__ A_in, const float* __restrict__ W,
    const float* __restrict__ bias, float* __restrict__ out_ext, int mode)
{
    __shared__ float As[32][132];   // [k][m], padded
    __shared__ float Ws[32][68];    // [k][n], padded

    const float* A = (mode == 3) ? g_att : A_in;
    const int tid = threadIdx.x;
    const int m0 = blockIdx.x * 128;
    const int n0 = blockIdx.y * 64;
    const int row_base = (tid >> 4) << 3;   // 0..120
    const int col_base = (tid & 15) << 2;   // 0..60

    float acc[8][4];
#pragma unroll
    for (int i = 0; i < 8; i++)
#pragma unroll
        for (int j = 0; j < 4; j++) acc[i][j] = 0.f;

    for (int k0 = 0; k0 < 512; k0 += 32) {
        // Load A tile 128x32 (transposed store into As[k][m])
#pragma unroll
        for (int i = 0; i < 4; i++) {
            int idx = tid + i * 256;          // 0..1023
            int r = idx >> 3;                 // 0..127
            int kk = (idx & 7) << 2;          // 0..28
            float4 v = *(const float4*)&A[(size_t)(m0 + r) * 512 + k0 + kk];
            As[kk + 0][r] = v.x;
            As[kk + 1][r] = v.y;
            As[kk + 2][r] = v.z;
            As[kk + 3][r] = v.w;
        }
        // Load W tile 32x64
#pragma unroll
        for (int i = 0; i < 2; i++) {
            int idx = tid + i * 256;          // 0..511
            int kk = idx >> 4;                // 0..31
            int cc = (idx & 15) << 2;         // 0..60
            *(float4*)&Ws[kk][cc] =
                *(const float4*)&W[(size_t)(k0 + kk) * 512 + n0 + cc];
        }
        __syncthreads();

#pragma unroll
        for (int kk = 0; kk < 32; kk++) {
            float4 a0 = *(const float4*)&As[kk][row_base];
            float4 a1 = *(const float4*)&As[kk][row_base + 4];
            float4 b4 = *(const float4*)&Ws[kk][col_base];
            float a[8] = {a0.x, a0.y, a0.z, a0.w, a1.x, a1.y, a1.z, a1.w};
            float bb[4] = {b4.x, b4.y, b4.z, b4.w};
#pragma unroll
            for (int i = 0; i < 8; i++)
#pragma unroll
                for (int j = 0; j < 4; j++) acc[i][j] += a[i] * bb[j];
        }
        __syncthreads();
    }

    if (mode < 3) {
        float* outb = (mode == 0) ? g_q : (mode == 1) ? g_k : g_v;
#pragma unroll
        for (int i = 0; i < 8; i++) {
            int r = m0 + row_base + i;        // global row = b*1024 + t
            int bb = r >> 10;
            int t = r & 1023;
#pragma unroll
            for (int j = 0; j < 4; j++) {
                int cidx = n0 + col_base + j; // h*64 + d
                int hh = cidx >> 6;
                int d = cidx & 63;
                outb[((((size_t)bb * H_SZ + hh) << 10) + t) * D_SZ + d] =
                    acc[i][j] + bias[cidx];
            }
        }
    } else {
#pragma unroll
        for (int i = 0; i < 8; i++) {
            int r = m0 + row_base + i;
#pragma unroll
            for (int j = 0; j < 4; j++) {
                int cidx = n0 + col_base + j;
                out_ext[(size_t)r * 512 + cidx] = acc[i][j] + bias[cidx];
            }
        }
    }
}

// ---------------------------------------------------------------------------
// Fused attention with banded relative-position bias + banded rel_v output.
// One block per (b, h, 64-query tile). Streams 64-key tiles, online softmax.
// ---------------------------------------------------------------------------
struct AttnSmem {
    float Qs[64][68];    // scaled Q tile
    float Ks[64][68];
    float Vs[64][68];
    float Ssm[64][68];   // scores, then unnormalized P
    float ek[9][64];     // emb_rel_k
    float ev[9][64];     // emb_rel_v
    float qe[64][12];    // qe[t][delta+4] = q_scaled[t] . ek[delta+4]
    float mrow[64];
    float lrow[64];
    float arow[64];
};

__global__ __launch_bounds__(256) void attn_kernel(const float* __restrict__ embk,
                                                   const float* __restrict__ embv)
{
    extern __shared__ char smem_raw[];
    AttnSmem& sm = *reinterpret_cast<AttnSmem*>(smem_raw);

    const int tid = threadIdx.x;
    const int qt0 = blockIdx.x * 64;
    const int h = blockIdx.y;
    const int b = blockIdx.z;
    const size_t head_off = ((size_t)(b * H_SZ + h)) * T_SZ * D_SZ;
    const float* Q = g_q + head_off;
    const float* K = g_k + head_off;
    const float* V = g_v + head_off;

    // Load Q (pre-scaled by 1/sqrt(64)) + embeddings
    for (int i = tid; i < 64 * 16; i += 256) {
        int r = i >> 4, d4 = (i & 15) << 2;
        float4 qv = *(const float4*)&Q[(size_t)(qt0 + r) * D_SZ + d4];
        sm.Qs[r][d4 + 0] = qv.x * 0.125f;
        sm.Qs[r][d4 + 1] = qv.y * 0.125f;
        sm.Qs[r][d4 + 2] = qv.z * 0.125f;
        sm.Qs[r][d4 + 3] = qv.w * 0.125f;
    }
    for (int i = tid; i < 9 * 64; i += 256) {
        sm.ek[0][i] = embk[i];   // ek rows are contiguous 64-float blocks
        sm.ev[0][i] = embv[i];
    }
    if (tid < 64) {
        sm.mrow[tid] = -1e30f;
        sm.lrow[tid] = 0.f;
    }
    __syncthreads();

    // qe[t][dd] = q_scaled[t] . ek[dd]   (covered by the sync inside the loop)
    for (int i = tid; i < 64 * 9; i += 256) {
        int t = i / 9, dd = i - t * 9;
        float s = 0.f;
#pragma unroll
        for (int d4 = 0; d4 < 64; d4 += 4) {
            float4 q4 = *(const float4*)&sm.Qs[t][d4];
            float4 e4 = *(const float4*)&sm.ek[dd][d4];
            s += q4.x * e4.x + q4.y * e4.y + q4.z * e4.z + q4.w * e4.w;
        }
        sm.qe[t][dd] = s;
    }

    float O[16];
#pragma unroll
    for (int j = 0; j < 16; j++) O[j] = 0.f;
    const int trow = tid >> 2;          // 0..63 (query row this thread works on)
    const int cseg = (tid & 3) << 4;    // 16-col / 16-d segment
    const int tglob = qt0 + trow;

    for (int s0 = 0; s0 < T_SZ; s0 += 64) {
        // Load K, V tiles
        for (int i = tid; i < 64 * 16; i += 256) {
            int r = i >> 4, d4 = (i & 15) << 2;
            *(float4*)&sm.Ks[r][d4] =
                *(const float4*)&K[(size_t)(s0 + r) * D_SZ + d4];
            *(float4*)&sm.Vs[r][d4] =
                *(const float4*)&V[(size_t)(s0 + r) * D_SZ + d4];
        }
        __syncthreads();

        // S = Qs . Ks^T  (each thread: 1 row x 16 cols)
        float acc[16];
#pragma unroll
        for (int cc = 0; cc < 16; cc++) acc[cc] = 0.f;
#pragma unroll 4
        for (int d4 = 0; d4 < 64; d4 += 4) {
            float4 q4 = *(const float4*)&sm.Qs[trow][d4];
#pragma unroll
            for (int cc = 0; cc < 16; cc++) {
                float4 k4 = *(const float4*)&sm.Ks[cseg + cc][d4];
                acc[cc] += q4.x * k4.x + q4.y * k4.y + q4.z * k4.z + q4.w * k4.w;
            }
        }
        // Banded relative-position bias
#pragma unroll
        for (int cc = 0; cc < 16; cc++) {
            int delta = s0 + cseg + cc - tglob;
            if (delta >= -4 && delta <= 4) acc[cc] += sm.qe[trow][delta + 4];
            sm.Ssm[trow][cseg + cc] = acc[cc];
        }
        __syncthreads();

        // Row max + rescale factor (one thread per row)
        if (tid < 64) {
            float mx = sm.mrow[tid];
            const float* row = sm.Ssm[tid];
#pragma unroll 8
            for (int s = 0; s < 64; s++) mx = fmaxf(mx, row[s]);
            sm.arow[tid] = __expf(sm.mrow[tid] - mx);
            sm.mrow[tid] = mx;
        }
        __syncthreads();

        // P = exp(S - m), partial row sums
        float mloc = sm.mrow[trow];
        float psum = 0.f;
#pragma unroll
        for (int cc = 0; cc < 16; cc++) {
            float p = __expf(sm.Ssm[trow][cseg + cc] - mloc);
            sm.Ssm[trow][cseg + cc] = p;
            psum += p;
        }
        psum += __shfl_xor_sync(0xffffffffu, psum, 1);
        psum += __shfl_xor_sync(0xffffffffu, psum, 2);
        if ((tid & 3) == 0)
            sm.lrow[trow] = sm.lrow[trow] * sm.arow[trow] + psum;
        __syncthreads();

        // O = O*alpha + P @ V  (each thread: 1 row x 16 d)
        float alpha = sm.arow[trow];
#pragma unroll
        for (int j = 0; j < 16; j++) O[j] *= alpha;
#pragma unroll 4
        for (int s = 0; s < 64; s++) {
            float p = sm.Ssm[trow][s];
#pragma unroll
            for (int j4 = 0; j4 < 16; j4 += 4) {
                float4 v4 = *(const float4*)&sm.Vs[s][cseg + j4];
                O[j4 + 0] += p * v4.x;
                O[j4 + 1] += p * v4.y;
                O[j4 + 2] += p * v4.z;
                O[j4 + 3] += p * v4.w;
            }
        }
        // Banded rel_v: O[t] += P[t, t+delta] * ev[delta+4]
#pragma unroll
        for (int dd = 0; dd < 9; dd++) {
            int sg = tglob + dd - 4;
            if (sg >= s0 && sg < s0 + 64 && sg >= 0 && sg < T_SZ) {
                float p = sm.Ssm[trow][sg - s0];
#pragma unroll
                for (int j4 = 0; j4 < 16; j4 += 4) {
                    float4 e4 = *(const float4*)&sm.ev[dd][cseg + j4];
                    O[j4 + 0] += p * e4.x;
                    O[j4 + 1] += p * e4.y;
                    O[j4 + 2] += p * e4.z;
                    O[j4 + 3] += p * e4.w;
                }
            }
        }
        __syncthreads();
    }

    // Normalize and write to g_att[b][t][h*64+d]
    float inv_l = 1.0f / sm.lrow[trow];
    float* dst = g_att + ((size_t)(b * T_SZ + tglob)) * C_SZ + h * D_SZ + cseg;
#pragma unroll
    for (int j = 0; j < 16; j++) dst[j] = O[j] * inv_l;
}

// ---------------------------------------------------------------------------
// Launch
// ---------------------------------------------------------------------------
extern "C" void kernel_launch(void* const* d_in, const int* in_sizes, int n_in,
                              void* d_out, int out_size)
{
    const float* x    = (const float*)d_in[0];
    const float* c    = (const float*)d_in[1];
    const float* Wq   = (const float*)d_in[2];
    const float* bq   = (const float*)d_in[3];
    const float* Wk   = (const float*)d_in[4];
    const float* bk   = (const float*)d_in[5];
    const float* Wv   = (const float*)d_in[6];
    const float* bv   = (const float*)d_in[7];
    const float* Wo   = (const float*)d_in[8];
    const float* bo   = (const float*)d_in[9];
    const float* embk = (const float*)d_in[10];
    const float* embv = (const float*)d_in[11];
    float* out = (float*)d_out;

    // Idempotent opt-in for >48KB dynamic smem (no stream interaction; capture-safe)
    (void)cudaFuncSetAttribute(attn_kernel,
                               cudaFuncAttributeMaxDynamicSharedMemorySize,
                               (int)sizeof(AttnSmem));

    dim3 gb(32, 8);
    gemm512_kernel<<<gb, 256>>>(x, Wq, bq, nullptr, 0);
    gemm512_kernel<<<gb, 256>>>(c, Wk, bk, nullptr, 1);
    gemm512_kernel<<<gb, 256>>>(c, Wv, bv, nullptr, 2);
    attn_kernel<<<dim3(T_SZ / 64, H_SZ, B_SZ), 256, sizeof(AttnSmem)>>>(embk, embv);
    gemm512_kernel<<<gb, 256>>>(nullptr, Wo, bo, out, 3);
}

// round 2
// speedup vs baseline: 5.6361x; 5.6361x over previous
#include <cuda_runtime.h>
#include <cuda_bf16.h>
#include <cstdint>

#define B_SZ 4
#define T_SZ 1024
#define C_SZ 512
#define H_SZ 8
#define D_SZ 64

// Scratch (static device globals — no allocation)
__device__ float g_q[B_SZ * H_SZ * T_SZ * D_SZ];
__device__ float g_k[B_SZ * H_SZ * T_SZ * D_SZ];
__device__ float g_v[B_SZ * H_SZ * T_SZ * D_SZ];
__device__ float g_att[B_SZ * T_SZ * C_SZ];

__device__ __forceinline__ uint32_t f2tf(float x) {
    uint32_t u;
    asm("cvt.rna.tf32.f32 %0, %1;" : "=r"(u) : "f"(x));
    return u;
}

__device__ __forceinline__ void mma_tf32(float c[4], const uint32_t a[4],
                                         const uint32_t b[2]) {
    asm volatile(
        "mma.sync.aligned.m16n8k8.row.col.f32.tf32.tf32.f32 "
        "{%0,%1,%2,%3}, {%4,%5,%6,%7}, {%8,%9}, {%0,%1,%2,%3};\n"
        : "+f"(c[0]), "+f"(c[1]), "+f"(c[2]), "+f"(c[3])
        : "r"(a[0]), "r"(a[1]), "r"(a[2]), "r"(a[3]), "r"(b[0]), "r"(b[1]));
}

// ---------------------------------------------------------------------------
// tf32 tensor-core GEMM: [4096 x 512] @ [512 x 512] + bias
// BM=128, BN=64, BK=32, 128 threads (4 warps, 2x2), warp tile 64x32.
// mode 0/1/2: write q/k/v in [b][h][t][d]; mode 3: A=g_att, row-major out.
// ---------------------------------------------------------------------------
__global__ __launch_bounds__(128) void gemm_tf32_kernel(
    const float* __restrict__ A_in, const float* __restrict__ W,
    const float* __restrict__ bias, float* __restrict__ out_ext, int mode)
{
    __shared__ uint32_t As[128][36];   // [m][k], tf32 bits
    __shared__ uint32_t Bs[32][68];    // [k][n], tf32 bits

    const float* A = (mode == 3) ? g_att : A_in;
    const int tid = threadIdx.x;
    const int lane = tid & 31;
    const int wid = tid >> 5;
    const int g = lane >> 2;     // groupID 0..7
    const int tg = lane & 3;     // threadID_in_group 0..3
    const int wm = wid >> 1;     // 0..1 -> 64-row half
    const int wn = wid & 1;      // 0..1 -> 32-col half
    const int m0 = blockIdx.x * 128;
    const int n0 = blockIdx.y * 64;

    float c[4][4][4];
#pragma unroll
    for (int i = 0; i < 4; i++)
#pragma unroll
        for (int j = 0; j < 4; j++)
#pragma unroll
            for (int q = 0; q < 4; q++) c[i][j][q] = 0.f;

    for (int k0 = 0; k0 < 512; k0 += 32) {
#pragma unroll
        for (int it = 0; it < 8; it++) {
            int idx = tid + it * 128;         // 0..1023
            int r = idx >> 3;                 // 0..127
            int kk = (idx & 7) << 2;          // 0..28
            float4 v = *(const float4*)&A[(size_t)(m0 + r) * 512 + k0 + kk];
            uint4 u = make_uint4(f2tf(v.x), f2tf(v.y), f2tf(v.z), f2tf(v.w));
            *(uint4*)&As[r][kk] = u;
        }
#pragma unroll
        for (int it = 0; it < 4; it++) {
            int idx = tid + it * 128;         // 0..511
            int kk = idx >> 4;                // 0..31
            int nn = (idx & 15) << 2;         // 0..60
            float4 v = *(const float4*)&W[(size_t)(k0 + kk) * 512 + n0 + nn];
            uint4 u = make_uint4(f2tf(v.x), f2tf(v.y), f2tf(v.z), f2tf(v.w));
            *(uint4*)&Bs[kk][nn] = u;
        }
        __syncthreads();

#pragma unroll
        for (int ks = 0; ks < 4; ks++) {
            int kb = ks * 8;
            uint32_t a[4][4], b[4][2];
#pragma unroll
            for (int i = 0; i < 4; i++) {
                int mr = wm * 64 + i * 16 + g;
                a[i][0] = As[mr][kb + tg];
                a[i][1] = As[mr + 8][kb + tg];
                a[i][2] = As[mr][kb + tg + 4];
                a[i][3] = As[mr + 8][kb + tg + 4];
            }
#pragma unroll
            for (int j = 0; j < 4; j++) {
                int nc = wn * 32 + j * 8 + g;
                b[j][0] = Bs[kb + tg][nc];
                b[j][1] = Bs[kb + tg + 4][nc];
            }
#pragma unroll
            for (int i = 0; i < 4; i++)
#pragma unroll
                for (int j = 0; j < 4; j++) mma_tf32(c[i][j], a[i], b[j]);
        }
        __syncthreads();
    }

    // Epilogue
#pragma unroll
    for (int i = 0; i < 4; i++) {
        int r0 = m0 + wm * 64 + i * 16 + g;
#pragma unroll
        for (int j = 0; j < 4; j++) {
            int col0 = n0 + wn * 32 + j * 8 + tg * 2;
            float v00 = c[i][j][0] + bias[col0];
            float v01 = c[i][j][1] + bias[col0 + 1];
            float v10 = c[i][j][2] + bias[col0];
            float v11 = c[i][j][3] + bias[col0 + 1];
            if (mode < 3) {
                float* outb = (mode == 0) ? g_q : (mode == 1) ? g_k : g_v;
                int hh = col0 >> 6;
                int d = col0 & 63;
                {
                    int bb = r0 >> 10, t = r0 & 1023;
                    size_t base = ((((size_t)bb * H_SZ + hh) << 10) + t) * D_SZ + d;
                    outb[base] = v00;
                    outb[base + 1] = v01;
                }
                {
                    int r1 = r0 + 8;
                    int bb = r1 >> 10, t = r1 & 1023;
                    size_t base = ((((size_t)bb * H_SZ + hh) << 10) + t) * D_SZ + d;
                    outb[base] = v10;
                    outb[base + 1] = v11;
                }
            } else {
                *(float2*)&out_ext[(size_t)r0 * 512 + col0] = make_float2(v00, v01);
                *(float2*)&out_ext[(size_t)(r0 + 8) * 512 + col0] = make_float2(v10, v11);
            }
        }
    }
}

// ---------------------------------------------------------------------------
// Fused flash attention with tf32 MMA for QK^T and PV, banded relative bias.
// One block per (b, h, 64-query tile), 128 threads (4 warps).
// ---------------------------------------------------------------------------
struct AttnSmem {
    uint32_t Qs[64][68];   // scaled Q, tf32 bits
    uint32_t Ks[64][68];   // K, tf32 bits
    uint32_t Vs[64][72];   // V, tf32 bits (stride 72: conflict-free B frags)
    float    S[64][68];    // scores -> P (tf32 bit pattern stored as float)
    float    Oex[64][68];  // banded rel_v accumulator (unnormalized, rescaled)
    float    ek[9][64];
    float    ev[9][64];
    float    qe[64][12];
    float    mrow[64], lrow[64], arow[64], linv[64];
};

__global__ __launch_bounds__(128) void attn_kernel(const float* __restrict__ embk,
                                                   const float* __restrict__ embv)
{
    extern __shared__ char smem_raw[];
    AttnSmem& sm = *reinterpret_cast<AttnSmem*>(smem_raw);

    const int tid = threadIdx.x;
    const int lane = tid & 31;
    const int wid = tid >> 5;           // 0..3
    const int g = lane >> 2;            // 0..7
    const int tg = lane & 3;            // 0..3
    const int w16 = wid * 16;
    const int qt0 = blockIdx.x * 64;
    const int h = blockIdx.y;
    const int b = blockIdx.z;
    const size_t head_off = ((size_t)(b * H_SZ + h)) * T_SZ * D_SZ;
    const float* Q = g_q + head_off;
    const float* K = g_k + head_off;
    const float* V = g_v + head_off;

    // Load Q (scaled, tf32), embeddings, init
    for (int i = tid; i < 64 * 16; i += 128) {
        int r = i >> 4, d4 = (i & 15) << 2;
        float4 qv = *(const float4*)&Q[(size_t)(qt0 + r) * D_SZ + d4];
        uint4 u = make_uint4(f2tf(qv.x * 0.125f), f2tf(qv.y * 0.125f),
                             f2tf(qv.z * 0.125f), f2tf(qv.w * 0.125f));
        *(uint4*)&sm.Qs[r][d4] = u;
    }
    for (int i = tid; i < 9 * 64; i += 128) {
        sm.ek[0][i] = embk[i];
        sm.ev[0][i] = embv[i];
    }
    for (int i = tid; i < 64 * 68; i += 128) sm.Oex[0][i] = 0.f;
    if (tid < 64) {
        sm.mrow[tid] = -1e30f;
        sm.lrow[tid] = 0.f;
    }
    __syncthreads();

    // qe[t][dd] = q_scaled[t] . ek[dd]
    for (int i = tid; i < 64 * 9; i += 128) {
        int t = i / 9, dd = i - t * 9;
        float s = 0.f;
        const float* qrow = (const float*)sm.Qs[t];
#pragma unroll
        for (int d = 0; d < 64; d += 4) {
            float4 q4 = *(const float4*)&qrow[d];
            float4 e4 = *(const float4*)&sm.ek[dd][d];
            s += q4.x * e4.x + q4.y * e4.y + q4.z * e4.z + q4.w * e4.w;
        }
        sm.qe[t][dd] = s;
    }

    float of[8][4];
#pragma unroll
    for (int n = 0; n < 8; n++)
#pragma unroll
        for (int q = 0; q < 4; q++) of[n][q] = 0.f;

    const int srow = tid >> 1;          // scalar-pass row 0..63
    const int half = tid & 1;           // 32-col half
    const int c0 = half * 32;

    for (int s0 = 0; s0 < T_SZ; s0 += 64) {
        // Load K, V tiles (tf32)
        for (int i = tid; i < 64 * 16; i += 128) {
            int r = i >> 4, d4 = (i & 15) << 2;
            float4 kv = *(const float4*)&K[(size_t)(s0 + r) * D_SZ + d4];
            float4 vv = *(const float4*)&V[(size_t)(s0 + r) * D_SZ + d4];
            *(uint4*)&sm.Ks[r][d4] =
                make_uint4(f2tf(kv.x), f2tf(kv.y), f2tf(kv.z), f2tf(kv.w));
            *(uint4*)&sm.Vs[r][d4] =
                make_uint4(f2tf(vv.x), f2tf(vv.y), f2tf(vv.z), f2tf(vv.w));
        }
        __syncthreads();

        // S = Qs . Ks^T  (MMA)
        float sc[8][4];
#pragma unroll
        for (int n = 0; n < 8; n++)
#pragma unroll
            for (int q = 0; q < 4; q++) sc[n][q] = 0.f;
#pragma unroll
        for (int ks = 0; ks < 8; ks++) {
            int kb = ks * 8;
            uint32_t a[4];
            a[0] = sm.Qs[w16 + g][kb + tg];
            a[1] = sm.Qs[w16 + g + 8][kb + tg];
            a[2] = sm.Qs[w16 + g][kb + tg + 4];
            a[3] = sm.Qs[w16 + g + 8][kb + tg + 4];
#pragma unroll
            for (int n = 0; n < 8; n++) {
                uint32_t bfr[2];
                bfr[0] = sm.Ks[n * 8 + g][kb + tg];
                bfr[1] = sm.Ks[n * 8 + g][kb + tg + 4];
                mma_tf32(sc[n], a, bfr);
            }
        }
        // Write S fragments
#pragma unroll
        for (int n = 0; n < 8; n++) {
            int col = n * 8 + tg * 2;
            sm.S[w16 + g][col] = sc[n][0];
            sm.S[w16 + g][col + 1] = sc[n][1];
            sm.S[w16 + g + 8][col] = sc[n][2];
            sm.S[w16 + g + 8][col + 1] = sc[n][3];
        }
        __syncthreads();

        // Pass 1: band bias + row max
        {
            float mx = -1e30f;
            int tglob = qt0 + srow;
#pragma unroll 8
            for (int cc = 0; cc < 32; cc++) {
                int col = c0 + cc;
                float v = sm.S[srow][col];
                int delta = s0 + col - tglob;
                if (delta >= -4 && delta <= 4) {
                    v += sm.qe[srow][delta + 4];
                    sm.S[srow][col] = v;
                }
                mx = fmaxf(mx, v);
            }
            mx = fmaxf(mx, __shfl_xor_sync(0xffffffffu, mx, 1));
            float newm = fmaxf(sm.mrow[srow], mx);
            if (half == 0) {
                sm.arow[srow] = __expf(sm.mrow[srow] - newm);
                sm.mrow[srow] = newm;
            }
        }
        __syncthreads();

        // Pass 2: exp -> P (tf32 bits), row sums, Oex rescale
        {
            float mloc = sm.mrow[srow];
            float alpha = sm.arow[srow];
            float psum = 0.f;
#pragma unroll 8
            for (int cc = 0; cc < 32; cc++) {
                int col = c0 + cc;
                float p = __expf(sm.S[srow][col] - mloc);
                uint32_t u = f2tf(p);
                sm.S[srow][col] = __uint_as_float(u);
                psum += __uint_as_float(u);
            }
            psum += __shfl_xor_sync(0xffffffffu, psum, 1);
            if (half == 0) sm.lrow[srow] = sm.lrow[srow] * alpha + psum;
#pragma unroll 8
            for (int cc = 0; cc < 32; cc++) sm.Oex[srow][c0 + cc] *= alpha;
        }
        __syncthreads();

        // Pass 3: banded rel_v into Oex
        {
            int tglob = qt0 + srow;
#pragma unroll
            for (int dd = 0; dd < 9; dd++) {
                int sg = tglob + dd - 4;
                if (sg >= s0 && sg < s0 + 64) {
                    float p = sm.S[srow][sg - s0];
#pragma unroll
                    for (int d4 = 0; d4 < 32; d4 += 4) {
                        float4 e4 = *(const float4*)&sm.ev[dd][c0 + d4];
                        float4 o4 = *(const float4*)&sm.Oex[srow][c0 + d4];
                        o4.x += p * e4.x;
                        o4.y += p * e4.y;
                        o4.z += p * e4.z;
                        o4.w += p * e4.w;
                        *(float4*)&sm.Oex[srow][c0 + d4] = o4;
                    }
                }
            }
        }

        // PV: rescale O frags by alpha, then O += P @ V (MMA)
        {
            float al0 = sm.arow[w16 + g];
            float al1 = sm.arow[w16 + g + 8];
#pragma unroll
            for (int n = 0; n < 8; n++) {
                of[n][0] *= al0;
                of[n][1] *= al0;
                of[n][2] *= al1;
                of[n][3] *= al1;
            }
#pragma unroll
            for (int ks = 0; ks < 8; ks++) {
                int kb = ks * 8;
                uint32_t a[4];
                a[0] = __float_as_uint(sm.S[w16 + g][kb + tg]);
                a[1] = __float_as_uint(sm.S[w16 + g + 8][kb + tg]);
                a[2] = __float_as_uint(sm.S[w16 + g][kb + tg + 4]);
                a[3] = __float_as_uint(sm.S[w16 + g + 8][kb + tg + 4]);
#pragma unroll
                for (int n = 0; n < 8; n++) {
                    uint32_t bfr[2];
                    bfr[0] = sm.Vs[kb + tg][n * 8 + g];
                    bfr[1] = sm.Vs[kb + tg + 4][n * 8 + g];
                    mma_tf32(of[n], a, bfr);
                }
            }
        }
        __syncthreads();
    }

    // Epilogue: normalize and write to g_att[b][t][h*64+d]
    if (tid < 64) sm.linv[tid] = 1.0f / sm.lrow[tid];
    __syncthreads();

    float l0 = sm.linv[w16 + g];
    float l1 = sm.linv[w16 + g + 8];
    int t0 = qt0 + w16 + g;
    int t1 = t0 + 8;
    float* base0 = g_att + ((size_t)(b * T_SZ + t0)) * C_SZ + h * D_SZ;
    float* base1 = g_att + ((size_t)(b * T_SZ + t1)) * C_SZ + h * D_SZ;
#pragma unroll
    for (int n = 0; n < 8; n++) {
        int col = n * 8 + tg * 2;
        float2 v0 = make_float2((of[n][0] + sm.Oex[w16 + g][col]) * l0,
                                (of[n][1] + sm.Oex[w16 + g][col + 1]) * l0);
        float2 v1 = make_float2((of[n][2] + sm.Oex[w16 + g + 8][col]) * l1,
                                (of[n][3] + sm.Oex[w16 + g + 8][col + 1]) * l1);
        *(float2*)&base0[col] = v0;
        *(float2*)&base1[col] = v1;
    }
}

// ---------------------------------------------------------------------------
// Launch
// ---------------------------------------------------------------------------
extern "C" void kernel_launch(void* const* d_in, const int* in_sizes, int n_in,
                              void* d_out, int out_size)
{
    const float* x    = (const float*)d_in[0];
    const float* c    = (const float*)d_in[1];
    const float* Wq   = (const float*)d_in[2];
    const float* bq   = (const float*)d_in[3];
    const float* Wk   = (const float*)d_in[4];
    const float* bk   = (const float*)d_in[5];
    const float* Wv   = (const float*)d_in[6];
    const float* bv   = (const float*)d_in[7];
    const float* Wo   = (const float*)d_in[8];
    const float* bo   = (const float*)d_in[9];
    const float* embk = (const float*)d_in[10];
    const float* embv = (const float*)d_in[11];
    float* out = (float*)d_out;

    (void)cudaFuncSetAttribute(attn_kernel,
                               cudaFuncAttributeMaxDynamicSharedMemorySize,
                               (int)sizeof(AttnSmem));

    dim3 gb(32, 8);
    gemm_tf32_kernel<<<gb, 128>>>(x, Wq, bq, nullptr, 0);
    gemm_tf32_kernel<<<gb, 128>>>(c, Wk, bk, nullptr, 1);
    gemm_tf32_kernel<<<gb, 128>>>(c, Wv, bv, nullptr, 2);
    attn_kernel<<<dim3(T_SZ / 64, H_SZ, B_SZ), 128, sizeof(AttnSmem)>>>(embk, embv);
    gemm_tf32_kernel<<<gb, 128>>>(nullptr, Wo, bo, out, 3);
}

// round 3
// speedup vs baseline: 8.5009x; 1.5083x over previous
#include <cuda_runtime.h>
#include <cuda_bf16.h>
#include <cstdint>

#define B_SZ 4
#define T_SZ 1024
#define C_SZ 512
#define H_SZ 8
#define D_SZ 64

// Q pre-scale: 1/sqrt(64) * log2(e)  (softmax done in exp2 domain)
#define Q_SCALE 0.18033688011112042f

__device__ float g_q[B_SZ * H_SZ * T_SZ * D_SZ];   // scaled + tf32-rounded
__device__ float g_k[B_SZ * H_SZ * T_SZ * D_SZ];   // tf32-rounded
__device__ float g_v[B_SZ * H_SZ * T_SZ * D_SZ];   // tf32-rounded
__device__ float g_att[B_SZ * T_SZ * C_SZ];

__device__ __forceinline__ uint32_t f2tf(float x) {
    uint32_t u;
    asm("cvt.rna.tf32.f32 %0, %1;" : "=r"(u) : "f"(x));
    return u;
}

__device__ __forceinline__ void mma_tf32(float c[4], const uint32_t a[4],
                                         uint32_t b0, uint32_t b1) {
    asm volatile(
        "mma.sync.aligned.m16n8k8.row.col.f32.tf32.tf32.f32 "
        "{%0,%1,%2,%3}, {%4,%5,%6,%7}, {%8,%9}, {%0,%1,%2,%3};\n"
        : "+f"(c[0]), "+f"(c[1]), "+f"(c[2]), "+f"(c[3])
        : "r"(a[0]), "r"(a[1]), "r"(a[2]), "r"(a[3]), "r"(b0), "r"(b1));
}

__device__ __forceinline__ void cp16(void* dst_smem, const void* src) {
    uint32_t d = (uint32_t)__cvta_generic_to_shared(dst_smem);
    asm volatile("cp.async.cg.shared.global [%0], [%1], 16;" :: "r"(d), "l"(src));
}

// ---------------------------------------------------------------------------
// tf32 tensor-core GEMM: [4096 x 512] @ [512 x 512] + bias
// ---------------------------------------------------------------------------
__global__ __launch_bounds__(128) void gemm_tf32_kernel(
    const float* __restrict__ A_in, const float* __restrict__ W,
    const float* __restrict__ bias, float* __restrict__ out_ext, int mode)
{
    __shared__ uint32_t As[128][36];
    __shared__ uint32_t Bs[32][68];

    const float* A = (mode == 3) ? g_att : A_in;
    const int tid = threadIdx.x;
    const int lane = tid & 31;
    const int wid = tid >> 5;
    const int g = lane >> 2;
    const int tg = lane & 3;
    const int wm = wid >> 1;
    const int wn = wid & 1;
    const int m0 = blockIdx.x * 128;
    const int n0 = blockIdx.y * 64;

    float c[4][4][4];
#pragma unroll
    for (int i = 0; i < 4; i++)
#pragma unroll
        for (int j = 0; j < 4; j++)
#pragma unroll
            for (int q = 0; q < 4; q++) c[i][j][q] = 0.f;

    for (int k0 = 0; k0 < 512; k0 += 32) {
#pragma unroll
        for (int it = 0; it < 8; it++) {
            int idx = tid + it * 128;
            int r = idx >> 3;
            int kk = (idx & 7) << 2;
            float4 v = *(const float4*)&A[(size_t)(m0 + r) * 512 + k0 + kk];
            *(uint4*)&As[r][kk] =
                make_uint4(f2tf(v.x), f2tf(v.y), f2tf(v.z), f2tf(v.w));
        }
#pragma unroll
        for (int it = 0; it < 4; it++) {
            int idx = tid + it * 128;
            int kk = idx >> 4;
            int nn = (idx & 15) << 2;
            float4 v = *(const float4*)&W[(size_t)(k0 + kk) * 512 + n0 + nn];
            *(uint4*)&Bs[kk][nn] =
                make_uint4(f2tf(v.x), f2tf(v.y), f2tf(v.z), f2tf(v.w));
        }
        __syncthreads();

#pragma unroll
        for (int ks = 0; ks < 4; ks++) {
            int kb = ks * 8;
            uint32_t a[4][4], b[4][2];
#pragma unroll
            for (int i = 0; i < 4; i++) {
                int mr = wm * 64 + i * 16 + g;
                a[i][0] = As[mr][kb + tg];
                a[i][1] = As[mr + 8][kb + tg];
                a[i][2] = As[mr][kb + tg + 4];
                a[i][3] = As[mr + 8][kb + tg + 4];
            }
#pragma unroll
            for (int j = 0; j < 4; j++) {
                int nc = wn * 32 + j * 8 + g;
                b[j][0] = Bs[kb + tg][nc];
                b[j][1] = Bs[kb + tg + 4][nc];
            }
#pragma unroll
            for (int i = 0; i < 4; i++)
#pragma unroll
                for (int j = 0; j < 4; j++) mma_tf32(c[i][j], a[i], b[j][0], b[j][1]);
        }
        __syncthreads();
    }

#pragma unroll
    for (int i = 0; i < 4; i++) {
        int r0 = m0 + wm * 64 + i * 16 + g;
#pragma unroll
        for (int j = 0; j < 4; j++) {
            int col0 = n0 + wn * 32 + j * 8 + tg * 2;
            float v00 = c[i][j][0] + bias[col0];
            float v01 = c[i][j][1] + bias[col0 + 1];
            float v10 = c[i][j][2] + bias[col0];
            float v11 = c[i][j][3] + bias[col0 + 1];
            if (mode < 3) {
                if (mode == 0) {
                    v00 *= Q_SCALE; v01 *= Q_SCALE; v10 *= Q_SCALE; v11 *= Q_SCALE;
                }
                v00 = __uint_as_float(f2tf(v00));
                v01 = __uint_as_float(f2tf(v01));
                v10 = __uint_as_float(f2tf(v10));
                v11 = __uint_as_float(f2tf(v11));
                float* outb = (mode == 0) ? g_q : (mode == 1) ? g_k : g_v;
                int hh = col0 >> 6;
                int d = col0 & 63;
                {
                    int bb = r0 >> 10, t = r0 & 1023;
                    size_t base = ((((size_t)bb * H_SZ + hh) << 10) + t) * D_SZ + d;
                    *(float2*)&outb[base] = make_float2(v00, v01);
                }
                {
                    int r1 = r0 + 8;
                    int bb = r1 >> 10, t = r1 & 1023;
                    size_t base = ((((size_t)bb * H_SZ + hh) << 10) + t) * D_SZ + d;
                    *(float2*)&outb[base] = make_float2(v10, v11);
                }
            } else {
                *(float2*)&out_ext[(size_t)r0 * 512 + col0] = make_float2(v00, v01);
                *(float2*)&out_ext[(size_t)(r0 + 8) * 512 + col0] = make_float2(v10, v11);
            }
        }
    }
}

// ---------------------------------------------------------------------------
// Flash attention v3: register-resident softmax per warp, double-buffered KV.
// Block: 128 threads (4 warps), 64-query tile; each warp owns 16 rows.
// ---------------------------------------------------------------------------
#define KSTR 68
#define VSTR 72

struct AttnSmem {
    uint32_t Ks[2][64][KSTR];   // K tiles (tf32 bits), buf0 reused as Q staging
    uint32_t Vs[2][64][VSTR];
    uint32_t Sw[4][16][KSTR];   // per-warp P buffer
    float ek[9][64];
    float ev[9][64];
    float qe[64][12];
};

__global__ __launch_bounds__(128) void attn_kernel(const float* __restrict__ embk,
                                                   const float* __restrict__ embv)
{
    extern __shared__ char smem_raw[];
    AttnSmem& sm = *reinterpret_cast<AttnSmem*>(smem_raw);

    const int tid = threadIdx.x;
    const int lane = tid & 31;
    const int wid = tid >> 5;
    const int g = lane >> 2;
    const int tg = lane & 3;
    const int w16 = wid * 16;
    const int qt0 = blockIdx.x * 64;
    const int h = blockIdx.y;
    const int b = blockIdx.z;
    const size_t head_off = ((size_t)(b * H_SZ + h)) * T_SZ * D_SZ;
    const float* Q = g_q + head_off;
    const float* K = g_k + head_off;
    const float* V = g_v + head_off;

    // ---- Prologue: stage Q into Ks[0], load embeddings ----
    for (int i = tid; i < 64 * 16; i += 128) {
        int r = i >> 4, c4 = (i & 15) << 2;
        *(uint4*)&sm.Ks[0][r][c4] = *(const uint4*)&Q[(size_t)(qt0 + r) * D_SZ + c4];
    }
    for (int i = tid; i < 9 * 64; i += 128) {
        sm.ek[0][i] = embk[i] * 1.4426950408889634f;  // ek in exp2 domain too?  NO:
    }
    // NOTE: q is already scaled by 1/8*log2e, and qe = q . ek must equal
    // (q_orig/8 . ek) * log2e. Since q already carries log2e, ek must be RAW.
    // Overwrite with raw values (cheap, correctness-critical).
    __syncthreads();
    for (int i = tid; i < 9 * 64; i += 128) {
        sm.ek[0][i] = embk[i];
        sm.ev[0][i] = embv[i];
    }
    __syncthreads();

    // qe[t][dd] = q_scaled[t] . ek[dd]   (q carries 0.125*log2e already)
    for (int i = tid; i < 64 * 9; i += 128) {
        int t = i / 9, dd = i - t * 9;
        const float* qrow = (const float*)sm.Ks[0][t];
        float s = 0.f;
#pragma unroll
        for (int d = 0; d < 64; d += 4) {
            float4 q4 = *(const float4*)&qrow[d];
            float4 e4 = *(const float4*)&sm.ek[dd][d];
            s += q4.x * e4.x + q4.y * e4.y + q4.z * e4.z + q4.w * e4.w;
        }
        sm.qe[t][dd] = s;
    }

    // Q A-fragments to registers (all 8 k-steps, reused for all 16 tiles)
    uint32_t qa[8][4];
#pragma unroll
    for (int ks = 0; ks < 8; ks++) {
        qa[ks][0] = sm.Ks[0][w16 + g][ks * 8 + tg];
        qa[ks][1] = sm.Ks[0][w16 + g + 8][ks * 8 + tg];
        qa[ks][2] = sm.Ks[0][w16 + g][ks * 8 + tg + 4];
        qa[ks][3] = sm.Ks[0][w16 + g + 8][ks * 8 + tg + 4];
    }
    __syncthreads();   // done with Q staging & qe writes

    // Issue tile 0 copy
#pragma unroll
    for (int i = 0; i < 8; i++) {
        int idx = tid + i * 128;
        int r = idx >> 4, c4 = (idx & 15) << 2;
        cp16(&sm.Ks[0][r][c4], &K[(size_t)r * D_SZ + c4]);
        cp16(&sm.Vs[0][r][c4], &V[(size_t)r * D_SZ + c4]);
    }
    asm volatile("cp.async.commit_group;" ::: "memory");

    float of[8][4];
#pragma unroll
    for (int n = 0; n < 8; n++)
#pragma unroll
        for (int q = 0; q < 4; q++) of[n][q] = 0.f;
    float m0 = -1e30f, m1 = -1e30f, l0 = 0.f, l1 = 0.f;

    const int rg0 = qt0 + w16 + g;       // global row of "row0"
    const int rg1 = rg0 + 8;

    for (int j = 0; j < 16; j++) {
        const int s0 = j * 64;
        if (j < 15) {
            const int s1 = s0 + 64;
#pragma unroll
            for (int i = 0; i < 8; i++) {
                int idx = tid + i * 128;
                int r = idx >> 4, c4 = (idx & 15) << 2;
                cp16(&sm.Ks[(j + 1) & 1][r][c4], &K[(size_t)(s1 + r) * D_SZ + c4]);
                cp16(&sm.Vs[(j + 1) & 1][r][c4], &V[(size_t)(s1 + r) * D_SZ + c4]);
            }
            asm volatile("cp.async.commit_group;" ::: "memory");
            asm volatile("cp.async.wait_group 1;" ::: "memory");
        } else {
            asm volatile("cp.async.wait_group 0;" ::: "memory");
        }
        __syncthreads();
        const int buf = j & 1;

        // ---- S = Q K^T ----
        float sc[8][4];
#pragma unroll
        for (int n = 0; n < 8; n++)
#pragma unroll
            for (int q = 0; q < 4; q++) sc[n][q] = 0.f;
#pragma unroll
        for (int ks = 0; ks < 8; ks++) {
            int kb = ks * 8;
#pragma unroll
            for (int n = 0; n < 8; n++) {
                uint32_t b0 = sm.Ks[buf][n * 8 + g][kb + tg];
                uint32_t b1 = sm.Ks[buf][n * 8 + g][kb + tg + 4];
                mma_tf32(sc[n], qa[ks], b0, b1);
            }
        }

        // ---- banded bias (only tiles intersecting the band) ----
        const bool band = (s0 < qt0 + w16 + 20) && (s0 + 64 > qt0 + w16 - 4);
        if (band) {
#pragma unroll
            for (int n = 0; n < 8; n++) {
#pragma unroll
                for (int e = 0; e < 2; e++) {
                    int col = s0 + n * 8 + tg * 2 + e;
                    int d0 = col - rg0 + 4;
                    if ((unsigned)d0 <= 8u) sc[n][e] += sm.qe[w16 + g][d0];
                    int d1 = col - rg1 + 4;
                    if ((unsigned)d1 <= 8u) sc[n][2 + e] += sm.qe[w16 + g + 8][d1];
                }
            }
        }

        // ---- row max (registers + quad shuffles) ----
        float mx0 = -1e30f, mx1 = -1e30f;
#pragma unroll
        for (int n = 0; n < 8; n++) {
            mx0 = fmaxf(mx0, fmaxf(sc[n][0], sc[n][1]));
            mx1 = fmaxf(mx1, fmaxf(sc[n][2], sc[n][3]));
        }
        mx0 = fmaxf(mx0, __shfl_xor_sync(0xffffffffu, mx0, 1));
        mx0 = fmaxf(mx0, __shfl_xor_sync(0xffffffffu, mx0, 2));
        mx1 = fmaxf(mx1, __shfl_xor_sync(0xffffffffu, mx1, 1));
        mx1 = fmaxf(mx1, __shfl_xor_sync(0xffffffffu, mx1, 2));
        float nm0 = fmaxf(m0, mx0), nm1 = fmaxf(m1, mx1);
        float al0 = exp2f(m0 - nm0), al1 = exp2f(m1 - nm1);
        m0 = nm0; m1 = nm1;
#pragma unroll
        for (int n = 0; n < 8; n++) {
            of[n][0] *= al0; of[n][1] *= al0;
            of[n][2] *= al1; of[n][3] *= al1;
        }

        // ---- exp2, tf32-round, row sum, store P to per-warp buffer ----
        float ps0 = 0.f, ps1 = 0.f;
#pragma unroll
        for (int n = 0; n < 8; n++) {
            uint32_t u0 = f2tf(exp2f(sc[n][0] - m0));
            uint32_t u1 = f2tf(exp2f(sc[n][1] - m0));
            uint32_t u2 = f2tf(exp2f(sc[n][2] - m1));
            uint32_t u3 = f2tf(exp2f(sc[n][3] - m1));
            ps0 += __uint_as_float(u0) + __uint_as_float(u1);
            ps1 += __uint_as_float(u2) + __uint_as_float(u3);
            *(uint2*)&sm.Sw[wid][g][n * 8 + tg * 2] = make_uint2(u0, u1);
            *(uint2*)&sm.Sw[wid][g + 8][n * 8 + tg * 2] = make_uint2(u2, u3);
        }
        ps0 += __shfl_xor_sync(0xffffffffu, ps0, 1);
        ps0 += __shfl_xor_sync(0xffffffffu, ps0, 2);
        ps1 += __shfl_xor_sync(0xffffffffu, ps1, 1);
        ps1 += __shfl_xor_sync(0xffffffffu, ps1, 2);
        l0 = l0 * al0 + ps0;
        l1 = l1 * al1 + ps1;
        __syncwarp();

        // ---- banded rel_v into O fragments ----
        if (band) {
#pragma unroll
            for (int dd = 0; dd < 9; dd++) {
                int sg0 = rg0 + dd - 4;
                if (sg0 >= s0 && sg0 < s0 + 64) {
                    float p = __uint_as_float(sm.Sw[wid][g][sg0 - s0]);
#pragma unroll
                    for (int n = 0; n < 8; n++) {
                        float2 e2 = *(const float2*)&sm.ev[dd][n * 8 + tg * 2];
                        of[n][0] += p * e2.x;
                        of[n][1] += p * e2.y;
                    }
                }
                int sg1 = rg1 + dd - 4;
                if (sg1 >= s0 && sg1 < s0 + 64) {
                    float p = __uint_as_float(sm.Sw[wid][g + 8][sg1 - s0]);
#pragma unroll
                    for (int n = 0; n < 8; n++) {
                        float2 e2 = *(const float2*)&sm.ev[dd][n * 8 + tg * 2];
                        of[n][2] += p * e2.x;
                        of[n][3] += p * e2.y;
                    }
                }
            }
        }

        // ---- O += P V ----
#pragma unroll
        for (int ks = 0; ks < 8; ks++) {
            int kb = ks * 8;
            uint32_t a[4];
            a[0] = sm.Sw[wid][g][kb + tg];
            a[1] = sm.Sw[wid][g + 8][kb + tg];
            a[2] = sm.Sw[wid][g][kb + tg + 4];
            a[3] = sm.Sw[wid][g + 8][kb + tg + 4];
#pragma unroll
            for (int n = 0; n < 8; n++) {
                uint32_t b0 = sm.Vs[buf][kb + tg][n * 8 + g];
                uint32_t b1 = sm.Vs[buf][kb + tg + 4][n * 8 + g];
                mma_tf32(of[n], a, b0, b1);
            }
        }
        __syncthreads();   // all warps done with buf before it is overwritten
    }

    // ---- Epilogue ----
    float li0 = 1.0f / l0, li1 = 1.0f / l1;
    float* base0 = g_att + ((size_t)(b * T_SZ + rg0)) * C_SZ + h * D_SZ;
    float* base1 = g_att + ((size_t)(b * T_SZ + rg1)) * C_SZ + h * D_SZ;
#pragma unroll
    for (int n = 0; n < 8; n++) {
        int col = n * 8 + tg * 2;
        *(float2*)&base0[col] = make_float2(of[n][0] * li0, of[n][1] * li0);
        *(float2*)&base1[col] = make_float2(of[n][2] * li1, of[n][3] * li1);
    }
}

// ---------------------------------------------------------------------------
// Launch
// ---------------------------------------------------------------------------
extern "C" void kernel_launch(void* const* d_in, const int* in_sizes, int n_in,
                              void* d_out, int out_size)
{
    const float* x    = (const float*)d_in[0];
    const float* c    = (const float*)d_in[1];
    const float* Wq   = (const float*)d_in[2];
    const float* bq   = (const float*)d_in[3];
    const float* Wk   = (const float*)d_in[4];
    const float* bk   = (const float*)d_in[5];
    const float* Wv   = (const float*)d_in[6];
    const float* bv   = (const float*)d_in[7];
    const float* Wo   = (const float*)d_in[8];
    const float* bo   = (const float*)d_in[9];
    const float* embk = (const float*)d_in[10];
    const float* embv = (const float*)d_in[11];
    float* out = (float*)d_out;

    (void)cudaFuncSetAttribute(attn_kernel,
                               cudaFuncAttributeMaxDynamicSharedMemorySize,
                               (int)sizeof(AttnSmem));

    dim3 gb(32, 8);
    gemm_tf32_kernel<<<gb, 128>>>(x, Wq, bq, nullptr, 0);
    gemm_tf32_kernel<<<gb, 128>>>(c, Wk, bk, nullptr, 1);
    gemm_tf32_kernel<<<gb, 128>>>(c, Wv, bv, nullptr, 2);
    attn_kernel<<<dim3(T_SZ / 64, H_SZ, B_SZ), 128, sizeof(AttnSmem)>>>(embk, embv);
    gemm_tf32_kernel<<<gb, 128>>>(nullptr, Wo, bo, out, 3);
}

// round 4
// speedup vs baseline: 10.1849x; 1.1981x over previous
#include <cuda_runtime.h>
#include <cstdint>

#define B_SZ 4
#define T_SZ 1024
#define C_SZ 512
#define H_SZ 8
#define D_SZ 64

// Q pre-scale: 1/sqrt(64) * log2(e)  (softmax in exp2 domain)
#define Q_SCALE 0.18033688011112042f

__device__ float g_q[B_SZ * H_SZ * T_SZ * D_SZ];   // scaled + tf32-rounded
__device__ float g_k[B_SZ * H_SZ * T_SZ * D_SZ];   // tf32-rounded
__device__ float g_v[B_SZ * H_SZ * T_SZ * D_SZ];   // tf32-rounded
__device__ float g_att[B_SZ * T_SZ * C_SZ];

__device__ __forceinline__ uint32_t f2tf(float x) {
    uint32_t u;
    asm("cvt.rna.tf32.f32 %0, %1;" : "=r"(u) : "f"(x));
    return u;
}

__device__ __forceinline__ float ex2(float x) {
    float y;
    asm("ex2.approx.ftz.f32 %0, %1;" : "=f"(y) : "f"(x));
    return y;
}

__device__ __forceinline__ void mma_tf32(float c[4], const uint32_t a[4],
                                         uint32_t b0, uint32_t b1) {
    asm volatile(
        "mma.sync.aligned.m16n8k8.row.col.f32.tf32.tf32.f32 "
        "{%0,%1,%2,%3}, {%4,%5,%6,%7}, {%8,%9}, {%0,%1,%2,%3};\n"
        : "+f"(c[0]), "+f"(c[1]), "+f"(c[2]), "+f"(c[3])
        : "r"(a[0]), "r"(a[1]), "r"(a[2]), "r"(a[3]), "r"(b0), "r"(b1));
}

__device__ __forceinline__ void cp16(void* dst_smem, const void* src) {
    uint32_t d = (uint32_t)__cvta_generic_to_shared(dst_smem);
    asm volatile("cp.async.cg.shared.global [%0], [%1], 16;" :: "r"(d), "l"(src));
}
#define CP_COMMIT() asm volatile("cp.async.commit_group;" ::: "memory")

// ---------------------------------------------------------------------------
// tf32 GEMM with cp.async double buffering.
// mode 0: fused QKV — grid (32, 24); blockIdx.y selects x/Wq, c/Wk, c/Wv.
// mode 3: output GEMM g_att @ Wo + bo — grid (32, 8).
// BM=128, BN=64, BK=32, 128 threads (4 warps 2x2), warp tile 64x32.
// ---------------------------------------------------------------------------
struct GemmSmem {
    float As[2][128][36];   // raw f32, [m][k]
    float Bs[2][32][72];    // raw f32, [k][n]
};

__global__ __launch_bounds__(128, 2) void gemm_tf32_kernel(
    const float* __restrict__ x, const float* __restrict__ cc,
    const float* __restrict__ Wq, const float* __restrict__ bq,
    const float* __restrict__ Wk, const float* __restrict__ bk,
    const float* __restrict__ Wv, const float* __restrict__ bv,
    const float* __restrict__ Wo, const float* __restrict__ bo,
    float* __restrict__ out_ext, int mode)
{
    extern __shared__ char raw[];
    GemmSmem& sm = *reinterpret_cast<GemmSmem*>(raw);

    const float* A; const float* W; const float* bias; int sel;
    int n0;
    if (mode == 0) {
        sel = blockIdx.y >> 3;
        A = (sel == 0) ? x : cc;
        W = (sel == 0) ? Wq : (sel == 1) ? Wk : Wv;
        bias = (sel == 0) ? bq : (sel == 1) ? bk : bv;
        n0 = (blockIdx.y & 7) * 64;
    } else {
        sel = 3;
        A = g_att; W = Wo; bias = bo;
        n0 = blockIdx.y * 64;
    }
    const int m0 = blockIdx.x * 128;
    const int tid = threadIdx.x;
    const int lane = tid & 31;
    const int wid = tid >> 5;
    const int g = lane >> 2;
    const int tg = lane & 3;
    const int wm = wid >> 1;
    const int wn = wid & 1;

    auto issue_tile = [&](int kt, int bufi) {
        int kb = kt * 32;
#pragma unroll
        for (int i = 0; i < 8; i++) {
            int idx = tid + i * 128;
            int r = idx >> 3;
            int kk = (idx & 7) << 2;
            cp16(&sm.As[bufi][r][kk], &A[(size_t)(m0 + r) * 512 + kb + kk]);
        }
#pragma unroll
        for (int i = 0; i < 4; i++) {
            int idx = tid + i * 128;
            int kk = idx >> 4;
            int nn = (idx & 15) << 2;
            cp16(&sm.Bs[bufi][kk][nn], &W[(size_t)(kb + kk) * 512 + n0 + nn]);
        }
        CP_COMMIT();
    };

    float c[4][4][4];
#pragma unroll
    for (int i = 0; i < 4; i++)
#pragma unroll
        for (int j = 0; j < 4; j++)
#pragma unroll
            for (int q = 0; q < 4; q++) c[i][j][q] = 0.f;

    issue_tile(0, 0);

    for (int kt = 0; kt < 16; kt++) {
        asm volatile("cp.async.wait_group 0;" ::: "memory");
        __syncthreads();                         // data visible; prev readers done
        if (kt < 15) issue_tile(kt + 1, (kt + 1) & 1);
        const float (*Af)[36] = sm.As[kt & 1];
        const float (*Bf)[72] = sm.Bs[kt & 1];

#pragma unroll
        for (int ks = 0; ks < 4; ks++) {
            int kb = ks * 8;
            uint32_t a[4][4], b[4][2];
#pragma unroll
            for (int i = 0; i < 4; i++) {
                int mr = wm * 64 + i * 16 + g;
                a[i][0] = f2tf(Af[mr][kb + tg]);
                a[i][1] = f2tf(Af[mr + 8][kb + tg]);
                a[i][2] = f2tf(Af[mr][kb + tg + 4]);
                a[i][3] = f2tf(Af[mr + 8][kb + tg + 4]);
            }
#pragma unroll
            for (int j = 0; j < 4; j++) {
                int nc = wn * 32 + j * 8 + g;
                b[j][0] = f2tf(Bf[kb + tg][nc]);
                b[j][1] = f2tf(Bf[kb + tg + 4][nc]);
            }
#pragma unroll
            for (int i = 0; i < 4; i++)
#pragma unroll
                for (int j = 0; j < 4; j++) mma_tf32(c[i][j], a[i], b[j][0], b[j][1]);
        }
    }

#pragma unroll
    for (int i = 0; i < 4; i++) {
        int r0 = m0 + wm * 64 + i * 16 + g;
#pragma unroll
        for (int j = 0; j < 4; j++) {
            int col0 = n0 + wn * 32 + j * 8 + tg * 2;
            float v00 = c[i][j][0] + bias[col0];
            float v01 = c[i][j][1] + bias[col0 + 1];
            float v10 = c[i][j][2] + bias[col0];
            float v11 = c[i][j][3] + bias[col0 + 1];
            if (sel < 3) {
                if (sel == 0) {
                    v00 *= Q_SCALE; v01 *= Q_SCALE; v10 *= Q_SCALE; v11 *= Q_SCALE;
                }
                v00 = __uint_as_float(f2tf(v00));
                v01 = __uint_as_float(f2tf(v01));
                v10 = __uint_as_float(f2tf(v10));
                v11 = __uint_as_float(f2tf(v11));
                float* outb = (sel == 0) ? g_q : (sel == 1) ? g_k : g_v;
                int hh = col0 >> 6;
                int d = col0 & 63;
                {
                    int bb = r0 >> 10, t = r0 & 1023;
                    size_t base = ((((size_t)bb * H_SZ + hh) << 10) + t) * D_SZ + d;
                    *(float2*)&outb[base] = make_float2(v00, v01);
                }
                {
                    int r1 = r0 + 8;
                    int bb = r1 >> 10, t = r1 & 1023;
                    size_t base = ((((size_t)bb * H_SZ + hh) << 10) + t) * D_SZ + d;
                    *(float2*)&outb[base] = make_float2(v10, v11);
                }
            } else {
                *(float2*)&out_ext[(size_t)r0 * 512 + col0] = make_float2(v00, v01);
                *(float2*)&out_ext[(size_t)(r0 + 8) * 512 + col0] = make_float2(v10, v11);
            }
        }
    }
}

// ---------------------------------------------------------------------------
// Flash attention v4: 62.5KB smem (3 CTAs/SM), shuffle-transposed P (no Sw),
// band[] array for rel_v, K double-buffered prefetch, V single-buffered.
// Block: 128 threads (4 warps), 64-query tile; warp owns 16 rows.
// ---------------------------------------------------------------------------
struct AttnSmem {
    uint32_t Ks[2][64][68];   // K tiles (tf32 bits); buf0 doubles as Q staging
    uint32_t Vs[64][72];      // V tile
    float ek[9][64];
    float ev[9][64];
    float qe[64][12];
    float band[64][12];       // banded P values for rel_v
};

__global__ __launch_bounds__(128, 3) void attn_kernel(const float* __restrict__ embk,
                                                      const float* __restrict__ embv)
{
    extern __shared__ char smem_raw[];
    AttnSmem& sm = *reinterpret_cast<AttnSmem*>(smem_raw);

    const int tid = threadIdx.x;
    const int lane = tid & 31;
    const int wid = tid >> 5;
    const int g = lane >> 2;
    const int tg = lane & 3;
    const int w16 = wid * 16;
    const int qt0 = blockIdx.x * 64;
    const int h = blockIdx.y;
    const int b = blockIdx.z;
    const size_t head_off = ((size_t)(b * H_SZ + h)) * T_SZ * D_SZ;
    const float* Q = g_q + head_off;
    const float* K = g_k + head_off;
    const float* V = g_v + head_off;

    // ---- Prologue: stage Q into Ks[0], load embeddings ----
    for (int i = tid; i < 64 * 16; i += 128) {
        int r = i >> 4, c4 = (i & 15) << 2;
        *(uint4*)&sm.Ks[0][r][c4] = *(const uint4*)&Q[(size_t)(qt0 + r) * D_SZ + c4];
    }
    for (int i = tid; i < 9 * 64; i += 128) {
        sm.ek[0][i] = embk[i];
        sm.ev[0][i] = embv[i];
    }
    __syncthreads();

    // qe[t][dd] = q_scaled[t] . ek[dd]  (q already carries 0.125*log2e)
    for (int i = tid; i < 64 * 9; i += 128) {
        int t = i / 9, dd = i - t * 9;
        const float* qrow = (const float*)sm.Ks[0][t];
        float s = 0.f;
#pragma unroll
        for (int d = 0; d < 64; d += 4) {
            float4 q4 = *(const float4*)&qrow[d];
            float4 e4 = *(const float4*)&sm.ek[dd][d];
            s += q4.x * e4.x + q4.y * e4.y + q4.z * e4.z + q4.w * e4.w;
        }
        sm.qe[t][dd] = s;
    }

    // Q A-fragments to registers
    uint32_t qa[8][4];
#pragma unroll
    for (int ks = 0; ks < 8; ks++) {
        qa[ks][0] = sm.Ks[0][w16 + g][ks * 8 + tg];
        qa[ks][1] = sm.Ks[0][w16 + g + 8][ks * 8 + tg];
        qa[ks][2] = sm.Ks[0][w16 + g][ks * 8 + tg + 4];
        qa[ks][3] = sm.Ks[0][w16 + g + 8][ks * 8 + tg + 4];
    }
    __syncthreads();   // Q reads & qe writes done before K0 overwrites Ks[0]

    // Prologue copies: K0 + V0 (one group)
#pragma unroll
    for (int i = 0; i < 8; i++) {
        int idx = tid + i * 128;
        int r = idx >> 4, c4 = (idx & 15) << 2;
        cp16(&sm.Ks[0][r][c4], &K[(size_t)r * D_SZ + c4]);
        cp16(&sm.Vs[r][c4], &V[(size_t)r * D_SZ + c4]);
    }
    CP_COMMIT();

    float of[8][4];
#pragma unroll
    for (int n = 0; n < 8; n++)
#pragma unroll
        for (int q = 0; q < 4; q++) of[n][q] = 0.f;
    float m0 = -1e30f, m1 = -1e30f, l0 = 0.f, l1 = 0.f;

    const int rg0 = qt0 + w16 + g;
    const int rg1 = rg0 + 8;

    for (int j = 0; j < 16; j++) {
        const int s0 = j * 64;
        // K(j+1) prefetch, then wait for K(j),V(j)
        if (j < 15) {
            const int s1 = s0 + 64;
#pragma unroll
            for (int i = 0; i < 8; i++) {
                int idx = tid + i * 128;
                int r = idx >> 4, c4 = (idx & 15) << 2;
                cp16(&sm.Ks[(j + 1) & 1][r][c4], &K[(size_t)(s1 + r) * D_SZ + c4]);
            }
            CP_COMMIT();
            asm volatile("cp.async.wait_group 1;" ::: "memory");
        } else {
            asm volatile("cp.async.wait_group 0;" ::: "memory");
        }
        __syncthreads();
        const int buf = j & 1;

        // ---- S = Q K^T ----
        float sc[8][4];
#pragma unroll
        for (int n = 0; n < 8; n++)
#pragma unroll
            for (int q = 0; q < 4; q++) sc[n][q] = 0.f;
#pragma unroll
        for (int ks = 0; ks < 8; ks++) {
            int kb = ks * 8;
#pragma unroll
            for (int n = 0; n < 8; n++) {
                uint32_t b0 = sm.Ks[buf][n * 8 + g][kb + tg];
                uint32_t b1 = sm.Ks[buf][n * 8 + g][kb + tg + 4];
                mma_tf32(sc[n], qa[ks], b0, b1);
            }
        }

        // ---- banded bias ----
        const bool band = (s0 < qt0 + w16 + 20) && (s0 + 64 > qt0 + w16 - 4);
        if (band) {
#pragma unroll
            for (int n = 0; n < 8; n++) {
#pragma unroll
                for (int e = 0; e < 2; e++) {
                    int col = s0 + n * 8 + tg * 2 + e;
                    int d0 = col - rg0 + 4;
                    if ((unsigned)d0 <= 8u) sc[n][e] += sm.qe[w16 + g][d0];
                    int d1 = col - rg1 + 4;
                    if ((unsigned)d1 <= 8u) sc[n][2 + e] += sm.qe[w16 + g + 8][d1];
                }
            }
        }

        // ---- row max ----
        float mx0 = -1e30f, mx1 = -1e30f;
#pragma unroll
        for (int n = 0; n < 8; n++) {
            mx0 = fmaxf(mx0, fmaxf(sc[n][0], sc[n][1]));
            mx1 = fmaxf(mx1, fmaxf(sc[n][2], sc[n][3]));
        }
        mx0 = fmaxf(mx0, __shfl_xor_sync(0xffffffffu, mx0, 1));
        mx0 = fmaxf(mx0, __shfl_xor_sync(0xffffffffu, mx0, 2));
        mx1 = fmaxf(mx1, __shfl_xor_sync(0xffffffffu, mx1, 1));
        mx1 = fmaxf(mx1, __shfl_xor_sync(0xffffffffu, mx1, 2));
        float nm0 = fmaxf(m0, mx0), nm1 = fmaxf(m1, mx1);
        float al0 = ex2(m0 - nm0), al1 = ex2(m1 - nm1);
        m0 = nm0; m1 = nm1;
#pragma unroll
        for (int n = 0; n < 8; n++) {
            of[n][0] *= al0; of[n][1] *= al0;
            of[n][2] *= al1; of[n][3] *= al1;
        }

        // ---- exp2 + tf32 round (P kept in sc), row sums, band writes ----
        float ps0 = 0.f, ps1 = 0.f;
#pragma unroll
        for (int n = 0; n < 8; n++) {
            float p0 = __uint_as_float(f2tf(ex2(sc[n][0] - m0)));
            float p1 = __uint_as_float(f2tf(ex2(sc[n][1] - m0)));
            float p2 = __uint_as_float(f2tf(ex2(sc[n][2] - m1)));
            float p3 = __uint_as_float(f2tf(ex2(sc[n][3] - m1)));
            sc[n][0] = p0; sc[n][1] = p1; sc[n][2] = p2; sc[n][3] = p3;
            ps0 += p0 + p1;
            ps1 += p2 + p3;
        }
        if (band) {
#pragma unroll
            for (int n = 0; n < 8; n++) {
#pragma unroll
                for (int e = 0; e < 2; e++) {
                    int col = s0 + n * 8 + tg * 2 + e;
                    int d0 = col - rg0 + 4;
                    if ((unsigned)d0 <= 8u) sm.band[w16 + g][d0] = sc[n][e];
                    int d1 = col - rg1 + 4;
                    if ((unsigned)d1 <= 8u) sm.band[w16 + g + 8][d1] = sc[n][2 + e];
                }
            }
        }
        ps0 += __shfl_xor_sync(0xffffffffu, ps0, 1);
        ps0 += __shfl_xor_sync(0xffffffffu, ps0, 2);
        ps1 += __shfl_xor_sync(0xffffffffu, ps1, 1);
        ps1 += __shfl_xor_sync(0xffffffffu, ps1, 2);
        l0 = l0 * al0 + ps0;
        l1 = l1 * al1 + ps1;

        // ---- banded rel_v from band[] ----
        if (band) {
            __syncwarp();
#pragma unroll
            for (int dd = 0; dd < 9; dd++) {
                int sg0 = rg0 + dd - 4;
                if (sg0 >= s0 && sg0 < s0 + 64) {
                    float p = sm.band[w16 + g][dd];
#pragma unroll
                    for (int n = 0; n < 8; n++) {
                        float2 e2 = *(const float2*)&sm.ev[dd][n * 8 + tg * 2];
                        of[n][0] += p * e2.x;
                        of[n][1] += p * e2.y;
                    }
                }
                int sg1 = rg1 + dd - 4;
                if (sg1 >= s0 && sg1 < s0 + 64) {
                    float p = sm.band[w16 + g + 8][dd];
#pragma unroll
                    for (int n = 0; n < 8; n++) {
                        float2 e2 = *(const float2*)&sm.ev[dd][n * 8 + tg * 2];
                        of[n][2] += p * e2.x;
                        of[n][3] += p * e2.y;
                    }
                }
            }
        }

        // ---- O += P V : transpose P via quad shuffles, MMA against Vs ----
        const int srcl = (lane & ~3) | (tg >> 1);
        const bool odd = (tg & 1);
#pragma unroll
        for (int ks = 0; ks < 8; ks++) {
            float v00 = __shfl_sync(0xffffffffu, sc[ks][0], srcl);
            float v01 = __shfl_sync(0xffffffffu, sc[ks][1], srcl);
            float v10 = __shfl_sync(0xffffffffu, sc[ks][2], srcl);
            float v11 = __shfl_sync(0xffffffffu, sc[ks][3], srcl);
            float v20 = __shfl_sync(0xffffffffu, sc[ks][0], srcl + 2);
            float v21 = __shfl_sync(0xffffffffu, sc[ks][1], srcl + 2);
            float v30 = __shfl_sync(0xffffffffu, sc[ks][2], srcl + 2);
            float v31 = __shfl_sync(0xffffffffu, sc[ks][3], srcl + 2);
            uint32_t a[4];
            a[0] = __float_as_uint(odd ? v01 : v00);
            a[1] = __float_as_uint(odd ? v11 : v10);
            a[2] = __float_as_uint(odd ? v21 : v20);
            a[3] = __float_as_uint(odd ? v31 : v30);
            int kb = ks * 8;
#pragma unroll
            for (int n = 0; n < 8; n++) {
                uint32_t b0 = sm.Vs[kb + tg][n * 8 + g];
                uint32_t b1 = sm.Vs[kb + tg + 4][n * 8 + g];
                mma_tf32(of[n], a, b0, b1);
            }
        }
        __syncthreads();   // all warps done with Vs (and band)

        // V(j+1) copy (single-buffered; exposure hidden across CTAs)
        if (j < 15) {
            const int s1 = s0 + 64;
#pragma unroll
            for (int i = 0; i < 8; i++) {
                int idx = tid + i * 128;
                int r = idx >> 4, c4 = (idx & 15) << 2;
                cp16(&sm.Vs[r][c4], &V[(size_t)(s1 + r) * D_SZ + c4]);
            }
            CP_COMMIT();
        }
    }

    // ---- Epilogue ----
    float li0 = 1.0f / l0, li1 = 1.0f / l1;
    float* base0 = g_att + ((size_t)(b * T_SZ + rg0)) * C_SZ + h * D_SZ;
    float* base1 = g_att + ((size_t)(b * T_SZ + rg1)) * C_SZ + h * D_SZ;
#pragma unroll
    for (int n = 0; n < 8; n++) {
        int col = n * 8 + tg * 2;
        *(float2*)&base0[col] = make_float2(of[n][0] * li0, of[n][1] * li0);
        *(float2*)&base1[col] = make_float2(of[n][2] * li1, of[n][3] * li1);
    }
}

// ---------------------------------------------------------------------------
// Launch
// ---------------------------------------------------------------------------
extern "C" void kernel_launch(void* const* d_in, const int* in_sizes, int n_in,
                              void* d_out, int out_size)
{
    const float* x    = (const float*)d_in[0];
    const float* c    = (const float*)d_in[1];
    const float* Wq   = (const float*)d_in[2];
    const float* bq   = (const float*)d_in[3];
    const float* Wk   = (const float*)d_in[4];
    const float* bk   = (const float*)d_in[5];
    const float* Wv   = (const float*)d_in[6];
    const float* bv   = (const float*)d_in[7];
    const float* Wo   = (const float*)d_in[8];
    const float* bo   = (const float*)d_in[9];
    const float* embk = (const float*)d_in[10];
    const float* embv = (const float*)d_in[11];
    float* out = (float*)d_out;

    (void)cudaFuncSetAttribute(attn_kernel,
                               cudaFuncAttributeMaxDynamicSharedMemorySize,
                               (int)sizeof(AttnSmem));
    (void)cudaFuncSetAttribute(gemm_tf32_kernel,
                               cudaFuncAttributeMaxDynamicSharedMemorySize,
                               (int)sizeof(GemmSmem));

    // Fused QKV projections
    gemm_tf32_kernel<<<dim3(32, 24), 128, sizeof(GemmSmem)>>>(
        x, c, Wq, bq, Wk, bk, Wv, bv, Wo, bo, nullptr, 0);
    // Attention
    attn_kernel<<<dim3(T_SZ / 64, H_SZ, B_SZ), 128, sizeof(AttnSmem)>>>(embk, embv);
    // Output projection
    gemm_tf32_kernel<<<dim3(32, 8), 128, sizeof(GemmSmem)>>>(
        x, c, Wq, bq, Wk, bk, Wv, bv, Wo, bo, out, 3);
}